// round 4
// baseline (speedup 1.0000x reference)
#include <cuda_runtime.h>
#include <math.h>

#define C1   32
#define C2   64
#define HDIM 64
#define CKK  288
#define IMG  96
#define TILE 32
#define NT   256

// ---- shared memory layout (float offsets) ----
#define XS_CS 111               // 3*37, odd-ish stride => conflict-light
#define XS_RS 37
#define O_XS   0
#define O_PHI  (O_XS + C1*XS_CS)       // 3552   (phi chunk: 144 x 64)
#define O_AT   (O_PHI + 144*64)        // 12768  (alpha_w^T, stride 68)
#define O_HS   (O_AT + 64*68)          // 17120  (h: 32 x 64)
#define O_ST   (O_HS + TILE*64)        // 19168  (stats: 32 x 8)
#define O_PROJ (O_ST + TILE*8)         // 19424
#define O_PBV  (O_PROJ + TILE)         // 19456
#define O_HIST (O_PBV + TILE)          // 19488  (32 x 16 ints)
#define O_FC1W (O_HIST + TILE*16)      // 20000
#define O_FC1B (O_FC1W + 320)          // 20320
#define O_PHIB (O_FC1B + 64)           // 20384
#define O_ALB  (O_PHIB + 288)          // 20672
#define O_BNI  (O_ALB + 64)
#define O_BNM  (O_BNI + 64)
#define O_BNB  (O_BNM + 64)
#define SMEM_F (O_BNB + 64)            // 20928 floats = 83712 bytes

__global__ __launch_bounds__(NT, 2) void sac_kernel(
    const float* __restrict__ x,       const float* __restrict__ fc1_w,
    const float* __restrict__ fc1_b,   const float* __restrict__ alpha_w,
    const float* __restrict__ alpha_b, const float* __restrict__ phi_w,
    const float* __restrict__ phi_b,   const float* __restrict__ bn_g,
    const float* __restrict__ bn_b,    const float* __restrict__ bn_m,
    const float* __restrict__ bn_v,    float* __restrict__ out)
{
    extern __shared__ float sm[];
    const int t    = threadIdx.x;
    const int jt   = blockIdx.x;
    const int irow = blockIdx.y;
    const int bz   = blockIdx.z;
    const int j0   = jt * TILE;
    float* xs = sm + O_XS;
    int* hist = (int*)(sm + O_HIST);

    // ---------------- Phase 0: stage tiles ----------------
    for (int idx = t; idx < C1 * XS_CS; idx += NT) {
        int c = idx / XS_CS, rem = idx - c * XS_CS;
        int kh = rem / XS_RS, col = rem - kh * XS_RS;
        int gr = irow - 1 + kh, gc = j0 - 1 + col;
        float v = 0.f;
        if (col < TILE + 2 && (unsigned)gr < IMG && (unsigned)gc < IMG)
            v = x[((bz * C1 + c) * IMG + gr) * IMG + gc];
        xs[idx] = v;
    }
    {   // phi_w rows [0,144) -> chunk buffer
        const float4* pw4 = (const float4*)phi_w;
        float4* ps4 = (float4*)(sm + O_PHI);
        for (int idx = t; idx < 144 * 64 / 4; idx += NT) ps4[idx] = pw4[idx];
    }
    for (int idx = t; idx < C2 * HDIM; idx += NT) {   // alpha_w^T, stride 68
        int c = idx >> 6, d = idx & 63;
        sm[O_AT + d * 68 + c] = alpha_w[idx];
    }
    for (int idx = t; idx < 320; idx += NT) sm[O_FC1W + idx] = fc1_w[idx];
    for (int idx = t; idx < 288; idx += NT) sm[O_PHIB + idx] = phi_b[idx];
    if (t < 64) {
        sm[O_FC1B + t] = fc1_b[t];
        sm[O_ALB  + t] = alpha_b[t];
        sm[O_BNI  + t] = bn_g[t] * rsqrtf(bn_v[t] + 1e-5f);
        sm[O_BNM  + t] = bn_m[t];
        sm[O_BNB  + t] = bn_b[t];
    }
    for (int idx = t; idx < TILE * 16; idx += NT) hist[idx] = 0;
    __syncthreads();

    // ---------------- Phase A: per-pixel statistics (8 threads/pixel) ----------------
    {
        const int px = t >> 3, sub = t & 7;
        float v[36];
        #pragma unroll
        for (int cc = 0; cc < 4; cc++) {
            const float* xb = xs + (sub * 4 + cc) * XS_CS + px;
            #pragma unroll
            for (int kh = 0; kh < 3; kh++)
                #pragma unroll
                for (int kw = 0; kw < 3; kw++)
                    v[cc * 9 + kh * 3 + kw] = xb[kh * XS_RS + kw];
        }
        float s0 = 0.f, mn = 3.4e38f, mx = -3.4e38f, pb = 0.f;
        #pragma unroll
        for (int i = 0; i < 36; i++) {
            s0 += v[i];
            mn = fminf(mn, v[i]);
            mx = fmaxf(mx, v[i]);
            pb += sm[O_PHIB + sub * 36 + i] * v[i];   // j = c*9 + kh*3 + kw
        }
        #pragma unroll
        for (int m = 1; m < 8; m <<= 1) {
            s0 += __shfl_xor_sync(0xffffffffu, s0, m);
            pb += __shfl_xor_sync(0xffffffffu, pb, m);
            mn = fminf(mn, __shfl_xor_sync(0xffffffffu, mn, m));
            mx = fmaxf(mx, __shfl_xor_sync(0xffffffffu, mx, m));
        }
        const float mu = s0 * (1.f / 288.f);
        const float rng = mx - mn + 1e-6f;
        float sd2 = 0.f;
        #pragma unroll
        for (int i = 0; i < 36; i++) {
            float d = v[i] - mu;
            sd2 += d * d;
            float pn = __fdiv_rn(v[i] - mn, rng);     // match ref binning exactly
            int b = (int)(pn * 15.0f);
            b = max(0, min(15, b));
            atomicAdd(&hist[px * 16 + b], 1);
        }
        #pragma unroll
        for (int m = 1; m < 8; m <<= 1) sd2 += __shfl_xor_sync(0xffffffffu, sd2, m);
        const float var   = sd2 * (1.f / 288.f);
        const float sigma = __fsqrt_rn(var + 1e-6f);
        const float zinv  = __fdiv_rn(1.f, sigma + 1e-6f);
        float s3 = 0.f, s4 = 0.f;
        #pragma unroll
        for (int i = 0; i < 36; i++) {
            float z = (v[i] - mu) * zinv, z2 = z * z;
            s3 += z2 * z;
            s4 += z2 * z2;
        }
        #pragma unroll
        for (int m = 1; m < 8; m <<= 1) {
            s3 += __shfl_xor_sync(0xffffffffu, s3, m);
            s4 += __shfl_xor_sync(0xffffffffu, s4, m);
        }
        __syncthreads();   // all histogram atomics visible
        float ent = 0.f;
        #pragma unroll
        for (int b = 0; b < 16; b++) {
            float p = (float)hist[px * 16 + b] * (1.f / 288.f);
            ent -= p * __logf(p + 1e-9f);
        }
        if (sub == 0) {
            sm[O_ST + px * 8 + 0] = mu;
            sm[O_ST + px * 8 + 1] = sigma;
            sm[O_ST + px * 8 + 2] = s3 * (1.f / 288.f);
            sm[O_ST + px * 8 + 3] = s4 * (1.f / 288.f) - 3.0f;
            sm[O_ST + px * 8 + 4] = ent;
            sm[O_PBV + px] = pb;
        }
    }
    __syncthreads();

    // ---------------- Phase B: MLP h = relu(fc1(s)) ----------------
    {
        const int px = t >> 3, d0 = (t & 7) * 8;
        const float s0 = sm[O_ST + px * 8 + 0], s1 = sm[O_ST + px * 8 + 1],
                    s2 = sm[O_ST + px * 8 + 2], s3 = sm[O_ST + px * 8 + 3],
                    s4 = sm[O_ST + px * 8 + 4];
        #pragma unroll
        for (int dd = 0; dd < 8; dd++) {
            int d = d0 + dd;
            const float* w = sm + O_FC1W + d * 5;
            float a = sm[O_FC1B + d] + s0 * w[0] + s1 * w[1] + s2 * w[2]
                      + s3 * w[3] + s4 * w[4];
            sm[O_HS + px * 64 + d] = fmaxf(a, 0.f);
        }
    }
    __syncthreads();

    // ---------------- Phase C: q-GEMM (32px x 64d x 288k), 2px x 4d / thread ----------------
    const int pr = t >> 4, dg = t & 15;
    const int px0 = pr * 2;
    float a00 = 0.f, a01 = 0.f, a02 = 0.f, a03 = 0.f;
    float a10 = 0.f, a11 = 0.f, a12 = 0.f, a13 = 0.f;
    {
        const float4* ph4 = (const float4*)(sm + O_PHI);
        for (int c = 0; c < 16; c++) {
            const float* xr = xs + c * XS_CS + px0;
            #pragma unroll
            for (int kh = 0; kh < 3; kh++)
                #pragma unroll
                for (int kw = 0; kw < 3; kw++) {
                    float q0 = xr[kh * XS_RS + kw];
                    float q1 = xr[kh * XS_RS + kw + 1];
                    float4 b = ph4[(c * 9 + kh * 3 + kw) * 16 + dg];
                    a00 += q0 * b.x; a01 += q0 * b.y; a02 += q0 * b.z; a03 += q0 * b.w;
                    a10 += q1 * b.x; a11 += q1 * b.y; a12 += q1 * b.z; a13 += q1 * b.w;
                }
        }
    }
    __syncthreads();
    {   // restage phi_w rows [144,288)
        const float4* pw4 = (const float4*)phi_w;
        float4* ps4 = (float4*)(sm + O_PHI);
        for (int idx = t; idx < 144 * 64 / 4; idx += NT) ps4[idx] = pw4[2304 + idx];
    }
    __syncthreads();
    {
        const float4* ph4 = (const float4*)(sm + O_PHI);
        for (int c = 16; c < 32; c++) {
            const float* xr = xs + c * XS_CS + px0;
            #pragma unroll
            for (int kh = 0; kh < 3; kh++)
                #pragma unroll
                for (int kw = 0; kw < 3; kw++) {
                    float q0 = xr[kh * XS_RS + kw];
                    float q1 = xr[kh * XS_RS + kw + 1];
                    float4 b = ph4[((c - 16) * 9 + kh * 3 + kw) * 16 + dg];
                    a00 += q0 * b.x; a01 += q0 * b.y; a02 += q0 * b.z; a03 += q0 * b.w;
                    a10 += q1 * b.x; a11 += q1 * b.y; a12 += q1 * b.z; a13 += q1 * b.w;
                }
        }
    }
    // epilogue: proj[px] = h . q + phi_b . patch   (16-lane shuffle reduce over dg)
    {
        const float4 h0 = *(const float4*)(sm + O_HS + px0 * 64 + dg * 4);
        float part = a00 * h0.x + a01 * h0.y + a02 * h0.z + a03 * h0.w;
        #pragma unroll
        for (int m = 1; m < 16; m <<= 1) part += __shfl_xor_sync(0xffffffffu, part, m);
        if (dg == 0) sm[O_PROJ + px0] = part + sm[O_PBV + px0];

        const float4 h1 = *(const float4*)(sm + O_HS + (px0 + 1) * 64 + dg * 4);
        float part1 = a10 * h1.x + a11 * h1.y + a12 * h1.z + a13 * h1.w;
        #pragma unroll
        for (int m = 1; m < 16; m <<= 1) part1 += __shfl_xor_sync(0xffffffffu, part1, m);
        if (dg == 0) sm[O_PROJ + px0 + 1] = part1 + sm[O_PBV + px0 + 1];
    }
    __syncthreads();

    // ---------------- Phase D: alpha GEMV + BN + SiLU + store ----------------
    {
        const int px = t >> 3, cb = (t & 7) * 8;
        const float prj = sm[O_PROJ + px];
        float ac[8] = {0.f, 0.f, 0.f, 0.f, 0.f, 0.f, 0.f, 0.f};
        const float* hp = sm + O_HS + px * 64;
        for (int d = 0; d < 64; d++) {
            float hd = hp[d];
            const float4 w0 = *(const float4*)(sm + O_AT + d * 68 + cb);
            const float4 w1 = *(const float4*)(sm + O_AT + d * 68 + cb + 4);
            ac[0] += hd * w0.x; ac[1] += hd * w0.y; ac[2] += hd * w0.z; ac[3] += hd * w0.w;
            ac[4] += hd * w1.x; ac[5] += hd * w1.y; ac[6] += hd * w1.z; ac[7] += hd * w1.w;
        }
        const int col = j0 + px;
        #pragma unroll
        for (int cc = 0; cc < 8; cc++) {
            int c = cb + cc;
            float al = ac[cc] + sm[O_ALB + c];
            float y  = (al * prj - sm[O_BNM + c]) * sm[O_BNI + c] + sm[O_BNB + c];
            float r  = y * __fdividef(1.f, 1.f + __expf(-y));
            out[((bz * C2 + c) * IMG + irow) * IMG + col] = r;
        }
    }
}

extern "C" void kernel_launch(void* const* d_in, const int* in_sizes, int n_in,
                              void* d_out, int out_size) {
    cudaFuncSetAttribute(sac_kernel, cudaFuncAttributeMaxDynamicSharedMemorySize,
                         SMEM_F * sizeof(float));
    dim3 grid(IMG / TILE, IMG, 4);
    sac_kernel<<<grid, NT, SMEM_F * sizeof(float)>>>(
        (const float*)d_in[0],  (const float*)d_in[1], (const float*)d_in[2],
        (const float*)d_in[3],  (const float*)d_in[4], (const float*)d_in[5],
        (const float*)d_in[6],  (const float*)d_in[7], (const float*)d_in[8],
        (const float*)d_in[9],  (const float*)d_in[10], (float*)d_out);
}

// round 5
// speedup vs baseline: 1.9722x; 1.9722x over previous
#include <cuda_runtime.h>
#include <math.h>

#define IMG 96
#define NT  256

#define XS_CS 217            // channel stride: 6 rows * 36 + 1 (conflict-free)
#define XS_RS 36
#define HS_ST 68

#define O_XS   0
#define O_PHI  (O_XS + 32*XS_CS)       // 6944   phi chunk 144x64 (36KB); reused for alphaT
#define O_HS   (O_PHI + 144*64)        // 16160  h: 128 x 68
#define O_ST   (O_HS + 128*HS_ST)      // 24864  stats: 128 x 8
#define O_PROJ (O_ST + 128*8)          // 25888
#define O_PBV  (O_PROJ + 128)          // 26016
#define O_FC1W (O_PBV + 128)           // 26144
#define O_FC1B (O_FC1W + 320)
#define O_PHIB (O_FC1B + 64)
#define O_ALB  (O_PHIB + 288)
#define O_BNI  (O_ALB + 64)
#define O_BNM  (O_BNI + 64)
#define O_BNB  (O_BNM + 64)
#define SMEM_F (O_BNB + 64)            // 27072 floats = 105.75 KB

// packed fp32x2 ops (sm_100+; ptxas never auto-fuses these)
#define PK2(d, lo, hi) asm("mov.b64 %0, {%1, %2};" : "=l"(d) : "r"(lo), "r"(hi))
#define UPK2(lo, hi, v) asm("mov.b64 {%0, %1}, %2;" : "=r"(lo), "=r"(hi) : "l"(v))
#define FMA2(d, a, b) asm("fma.rn.f32x2 %0, %1, %2, %3;" : "=l"(d) : "l"(a), "l"(b), "l"(d))

__global__ __launch_bounds__(NT, 2) void sac_kernel(
    const float* __restrict__ x,       const float* __restrict__ fc1_w,
    const float* __restrict__ fc1_b,   const float* __restrict__ alpha_w,
    const float* __restrict__ alpha_b, const float* __restrict__ phi_w,
    const float* __restrict__ phi_b,   const float* __restrict__ bn_g,
    const float* __restrict__ bn_b,    const float* __restrict__ bn_m,
    const float* __restrict__ bn_v,    float* __restrict__ out)
{
    extern __shared__ float sm[];
    const int t  = threadIdx.x;
    const int jt = blockIdx.x;          // col tile: j0 = jt*32
    const int it = blockIdx.y;          // row tile: irow0 = it*4
    const int bz = blockIdx.z;
    const int j0 = jt * 32;
    float* xs = sm + O_XS;

    // ---------------- Phase 0: stage ----------------
    for (int idx = t; idx < 32 * 216; idx += NT) {
        int c = idx / 216, rem = idx - c * 216;
        int r = rem / 36,  col = rem - r * 36;
        int gr = it * 4 - 1 + r, gc = j0 - 1 + col;
        float v = 0.f;
        if (col < 34 && (unsigned)gr < IMG && (unsigned)gc < IMG)
            v = x[((bz * 32 + c) * IMG + gr) * IMG + gc];
        xs[c * XS_CS + r * XS_RS + col] = v;
    }
    {   // phi rows [0,144)
        const float4* pw4 = (const float4*)phi_w;
        float4* ps4 = (float4*)(sm + O_PHI);
        for (int idx = t; idx < 2304; idx += NT) ps4[idx] = pw4[idx];
    }
    for (int idx = t; idx < 320; idx += NT) sm[O_FC1W + idx] = fc1_w[idx];
    for (int idx = t; idx < 288; idx += NT) sm[O_PHIB + idx] = phi_b[idx];
    if (t < 64) {
        sm[O_FC1B + t] = fc1_b[t];
        sm[O_ALB  + t] = alpha_b[t];
        sm[O_BNI  + t] = bn_g[t] * rsqrtf(bn_v[t] + 1e-5f);
        sm[O_BNM  + t] = bn_m[t];
        sm[O_BNB  + t] = bn_b[t];
    }
    __syncthreads();

    // ---------------- Phase A: stats, 8 thr/px, 4 passes of 32 px ----------------
    {
        const int sub = t & 7;
        #pragma unroll 1
        for (int it4 = 0; it4 < 4; it4++) {
            const int pxl = it4 * 32 + (t >> 3);
            const int ra = pxl >> 5, ca = pxl & 31;
            float v[36];
            #pragma unroll
            for (int cc = 0; cc < 4; cc++) {
                const float* xb = xs + (sub * 4 + cc) * XS_CS + ra * XS_RS + ca;
                #pragma unroll
                for (int kh = 0; kh < 3; kh++)
                    #pragma unroll
                    for (int kw = 0; kw < 3; kw++)
                        v[cc * 9 + kh * 3 + kw] = xb[kh * XS_RS + kw];
            }
            float s0 = 0.f, mn = 3.4e38f, mx = -3.4e38f, pb = 0.f;
            #pragma unroll
            for (int i = 0; i < 36; i++) {
                s0 += v[i];
                mn = fminf(mn, v[i]);
                mx = fmaxf(mx, v[i]);
                pb += sm[O_PHIB + sub * 36 + i] * v[i];
            }
            #pragma unroll
            for (int m = 1; m < 8; m <<= 1) {
                s0 += __shfl_xor_sync(0xffffffffu, s0, m);
                pb += __shfl_xor_sync(0xffffffffu, pb, m);
                mn = fminf(mn, __shfl_xor_sync(0xffffffffu, mn, m));
                mx = fmaxf(mx, __shfl_xor_sync(0xffffffffu, mx, m));
            }
            const float mu  = s0 * (1.f / 288.f);
            const float rng = mx - mn + 1e-6f;
            float sd2 = 0.f;
            unsigned long long hl = 0ull, hh = 0ull;
            #pragma unroll
            for (int i = 0; i < 36; i++) {
                float d = v[i] - mu;
                sd2 += d * d;
                float pn = __fdiv_rn(v[i] - mn, rng);
                int b = (int)(pn * 15.0f);
                b = max(0, min(15, b));
                unsigned long long one = 1ull << ((b & 7) * 8);
                hl += (b < 8) ? one : 0ull;
                hh += (b < 8) ? 0ull : one;
            }
            #pragma unroll
            for (int m = 1; m < 8; m <<= 1) sd2 += __shfl_xor_sync(0xffffffffu, sd2, m);
            const float var   = sd2 * (1.f / 288.f);
            const float sigma = __fsqrt_rn(var + 1e-6f);
            const float zinv  = __fdiv_rn(1.f, sigma + 1e-6f);
            float s3 = 0.f, s4 = 0.f;
            #pragma unroll
            for (int i = 0; i < 36; i++) {
                float z = (v[i] - mu) * zinv, z2 = z * z;
                s3 += z2 * z;
                s4 += z2 * z2;
            }
            // histogram reduce: widen 8-bit fields to 16-bit, butterfly over 8 lanes
            const unsigned long long M8 = 0x00FF00FF00FF00FFull;
            unsigned long long wl0 = hl & M8, wl1 = (hl >> 8) & M8;
            unsigned long long wh0 = hh & M8, wh1 = (hh >> 8) & M8;
            #pragma unroll
            for (int m = 1; m < 8; m <<= 1) {
                s3  += __shfl_xor_sync(0xffffffffu, s3, m);
                s4  += __shfl_xor_sync(0xffffffffu, s4, m);
                wl0 += __shfl_xor_sync(0xffffffffu, wl0, m);
                wl1 += __shfl_xor_sync(0xffffffffu, wl1, m);
                wh0 += __shfl_xor_sync(0xffffffffu, wh0, m);
                wh1 += __shfl_xor_sync(0xffffffffu, wh1, m);
            }
            // entropy: 2 bins per lane, butterfly sum
            unsigned long long wa = (sub & 2) ? wl1 : wl0;
            unsigned long long wb = (sub & 2) ? wh1 : wh0;
            unsigned long long w  = (sub & 4) ? wb : wa;
            unsigned int c0 = (unsigned int)(w >> ((sub & 1) * 32)) & 0xFFFFu;
            unsigned int c1 = (unsigned int)(w >> ((sub & 1) * 32 + 16)) & 0xFFFFu;
            float p0 = (float)c0 * (1.f / 288.f), p1 = (float)c1 * (1.f / 288.f);
            float ent = -(p0 * __logf(p0 + 1e-9f) + p1 * __logf(p1 + 1e-9f));
            #pragma unroll
            for (int m = 1; m < 8; m <<= 1) ent += __shfl_xor_sync(0xffffffffu, ent, m);
            if (sub == 0) {
                sm[O_ST + pxl * 8 + 0] = mu;
                sm[O_ST + pxl * 8 + 1] = sigma;
                sm[O_ST + pxl * 8 + 2] = s3 * (1.f / 288.f);
                sm[O_ST + pxl * 8 + 3] = s4 * (1.f / 288.f) - 3.0f;
                sm[O_ST + pxl * 8 + 4] = ent;
                sm[O_PBV + pxl] = pb;
            }
        }
    }
    __syncthreads();

    // ---------------- Phase B: h = relu(fc1(s)), 2 thr/px ----------------
    {
        const int px = t >> 1, d0 = (t & 1) * 32;
        const float s0 = sm[O_ST + px * 8 + 0], s1 = sm[O_ST + px * 8 + 1],
                    s2 = sm[O_ST + px * 8 + 2], s3 = sm[O_ST + px * 8 + 3],
                    s4 = sm[O_ST + px * 8 + 4];
        #pragma unroll 8
        for (int dd = 0; dd < 32; dd++) {
            int d = d0 + dd;
            const float* wp = sm + O_FC1W + d * 5;
            float a = sm[O_FC1B + d] + s0 * wp[0] + s1 * wp[1] + s2 * wp[2]
                      + s3 * wp[3] + s4 * wp[4];
            sm[O_HS + px * HS_ST + d] = fmaxf(a, 0.f);
        }
    }
    __syncthreads();

    // ---------------- Phase C: q-GEMM 128px x 64d x 288k, f32x2, 8px x 4d/thread ----------------
    const int pg = t >> 4, dg = t & 15;
    const int rr = pg >> 2, col0 = (pg & 3) * 8;
    const int d0 = dg * 4;
    unsigned long long acc[4][4];
    #pragma unroll
    for (int d = 0; d < 4; d++)
        #pragma unroll
        for (int pr = 0; pr < 4; pr++) acc[d][pr] = 0ull;

    const float4* ph4 = (const float4*)(sm + O_PHI);
    #pragma unroll 1
    for (int c = 0; c < 16; c++) {
        const float* xc = xs + c * XS_CS + rr * XS_RS + col0;
        #pragma unroll
        for (int kh = 0; kh < 3; kh++) {
            float seg[10];
            #pragma unroll
            for (int i = 0; i < 10; i++) seg[i] = xc[kh * XS_RS + i];
            #pragma unroll
            for (int kw = 0; kw < 3; kw++) {
                float4 b = ph4[(c * 9 + kh * 3 + kw) * 16 + dg];
                unsigned long long bd0, bd1, bd2, bd3, a0, a1, a2, a3;
                PK2(bd0, __float_as_uint(b.x), __float_as_uint(b.x));
                PK2(bd1, __float_as_uint(b.y), __float_as_uint(b.y));
                PK2(bd2, __float_as_uint(b.z), __float_as_uint(b.z));
                PK2(bd3, __float_as_uint(b.w), __float_as_uint(b.w));
                PK2(a0, __float_as_uint(seg[kw + 0]), __float_as_uint(seg[kw + 1]));
                PK2(a1, __float_as_uint(seg[kw + 2]), __float_as_uint(seg[kw + 3]));
                PK2(a2, __float_as_uint(seg[kw + 4]), __float_as_uint(seg[kw + 5]));
                PK2(a3, __float_as_uint(seg[kw + 6]), __float_as_uint(seg[kw + 7]));
                FMA2(acc[0][0], a0, bd0); FMA2(acc[0][1], a1, bd0);
                FMA2(acc[0][2], a2, bd0); FMA2(acc[0][3], a3, bd0);
                FMA2(acc[1][0], a0, bd1); FMA2(acc[1][1], a1, bd1);
                FMA2(acc[1][2], a2, bd1); FMA2(acc[1][3], a3, bd1);
                FMA2(acc[2][0], a0, bd2); FMA2(acc[2][1], a1, bd2);
                FMA2(acc[2][2], a2, bd2); FMA2(acc[2][3], a3, bd2);
                FMA2(acc[3][0], a0, bd3); FMA2(acc[3][1], a1, bd3);
                FMA2(acc[3][2], a2, bd3); FMA2(acc[3][3], a3, bd3);
            }
        }
    }
    __syncthreads();
    {   // restage phi rows [144,288)
        const float4* pw4 = (const float4*)phi_w;
        float4* ps4 = (float4*)(sm + O_PHI);
        for (int idx = t; idx < 2304; idx += NT) ps4[idx] = pw4[2304 + idx];
    }
    __syncthreads();
    #pragma unroll 1
    for (int c = 0; c < 16; c++) {
        const float* xc = xs + (c + 16) * XS_CS + rr * XS_RS + col0;
        #pragma unroll
        for (int kh = 0; kh < 3; kh++) {
            float seg[10];
            #pragma unroll
            for (int i = 0; i < 10; i++) seg[i] = xc[kh * XS_RS + i];
            #pragma unroll
            for (int kw = 0; kw < 3; kw++) {
                float4 b = ph4[(c * 9 + kh * 3 + kw) * 16 + dg];
                unsigned long long bd0, bd1, bd2, bd3, a0, a1, a2, a3;
                PK2(bd0, __float_as_uint(b.x), __float_as_uint(b.x));
                PK2(bd1, __float_as_uint(b.y), __float_as_uint(b.y));
                PK2(bd2, __float_as_uint(b.z), __float_as_uint(b.z));
                PK2(bd3, __float_as_uint(b.w), __float_as_uint(b.w));
                PK2(a0, __float_as_uint(seg[kw + 0]), __float_as_uint(seg[kw + 1]));
                PK2(a1, __float_as_uint(seg[kw + 2]), __float_as_uint(seg[kw + 3]));
                PK2(a2, __float_as_uint(seg[kw + 4]), __float_as_uint(seg[kw + 5]));
                PK2(a3, __float_as_uint(seg[kw + 6]), __float_as_uint(seg[kw + 7]));
                FMA2(acc[0][0], a0, bd0); FMA2(acc[0][1], a1, bd0);
                FMA2(acc[0][2], a2, bd0); FMA2(acc[0][3], a3, bd0);
                FMA2(acc[1][0], a0, bd1); FMA2(acc[1][1], a1, bd1);
                FMA2(acc[1][2], a2, bd1); FMA2(acc[1][3], a3, bd1);
                FMA2(acc[2][0], a0, bd2); FMA2(acc[2][1], a1, bd2);
                FMA2(acc[2][2], a2, bd2); FMA2(acc[2][3], a3, bd2);
                FMA2(acc[3][0], a0, bd3); FMA2(acc[3][1], a1, bd3);
                FMA2(acc[3][2], a2, bd3); FMA2(acc[3][3], a3, bd3);
            }
        }
    }
    // epilogue: proj[px] = h.q + phi_b.patch, reduce over 16 dg lanes
    {
        #pragma unroll
        for (int pr = 0; pr < 4; pr++) {
            const int pxl = rr * 32 + col0 + 2 * pr;
            const float4 hl4 = *(const float4*)(sm + O_HS + pxl * HS_ST + d0);
            const float4 hh4 = *(const float4*)(sm + O_HS + (pxl + 1) * HS_ST + d0);
            float hl[4] = {hl4.x, hl4.y, hl4.z, hl4.w};
            float hh[4] = {hh4.x, hh4.y, hh4.z, hh4.w};
            float lo = 0.f, hi = 0.f;
            #pragma unroll
            for (int d = 0; d < 4; d++) {
                unsigned int ql, qh;
                UPK2(ql, qh, acc[d][pr]);
                lo += __uint_as_float(ql) * hl[d];
                hi += __uint_as_float(qh) * hh[d];
            }
            #pragma unroll
            for (int m = 1; m < 16; m <<= 1) {
                lo += __shfl_xor_sync(0xffffffffu, lo, m);
                hi += __shfl_xor_sync(0xffffffffu, hi, m);
            }
            if (dg == 0) {
                sm[O_PROJ + pxl]     = lo + sm[O_PBV + pxl];
                sm[O_PROJ + pxl + 1] = hi + sm[O_PBV + pxl + 1];
            }
        }
    }
    __syncthreads();

    // stage alpha_w^T into dead phi buffer (stride 68)
    for (int idx = t; idx < 64 * 64; idx += NT) {
        int c = idx >> 6, d = idx & 63;
        sm[O_PHI + d * 68 + c] = alpha_w[idx];
    }
    __syncthreads();

    // ---------------- Phase D: alpha GEMV (f32x2) + BN + SiLU + store ----------------
    {
        const int pxg = t >> 3, cg = t & 7;
        const int px0 = pxg * 4, c0 = cg * 8;
        unsigned long long ac[8][2];
        #pragma unroll
        for (int ci = 0; ci < 8; ci++) { ac[ci][0] = 0ull; ac[ci][1] = 0ull; }
        #pragma unroll 4
        for (int d = 0; d < 64; d++) {
            float h0 = sm[O_HS + (px0 + 0) * HS_ST + d];
            float h1 = sm[O_HS + (px0 + 1) * HS_ST + d];
            float h2 = sm[O_HS + (px0 + 2) * HS_ST + d];
            float h3 = sm[O_HS + (px0 + 3) * HS_ST + d];
            unsigned long long hp0, hp1;
            PK2(hp0, __float_as_uint(h0), __float_as_uint(h1));
            PK2(hp1, __float_as_uint(h2), __float_as_uint(h3));
            const float4 w0 = *(const float4*)(sm + O_PHI + d * 68 + c0);
            const float4 w1 = *(const float4*)(sm + O_PHI + d * 68 + c0 + 4);
            float wv[8] = {w0.x, w0.y, w0.z, w0.w, w1.x, w1.y, w1.z, w1.w};
            #pragma unroll
            for (int ci = 0; ci < 8; ci++) {
                unsigned long long wd;
                PK2(wd, __float_as_uint(wv[ci]), __float_as_uint(wv[ci]));
                FMA2(ac[ci][0], hp0, wd);
                FMA2(ac[ci][1], hp1, wd);
            }
        }
        const float p0 = sm[O_PROJ + px0 + 0], p1 = sm[O_PROJ + px0 + 1];
        const float p2 = sm[O_PROJ + px0 + 2], p3 = sm[O_PROJ + px0 + 3];
        const int row  = it * 4 + (pxg >> 3);
        const int gcol = j0 + (pxg & 7) * 4;
        #pragma unroll
        for (int ci = 0; ci < 8; ci++) {
            const int c = c0 + ci;
            unsigned int u0, u1, u2, u3;
            UPK2(u0, u1, ac[ci][0]);
            UPK2(u2, u3, ac[ci][1]);
            const float alb = sm[O_ALB + c], bni = sm[O_BNI + c];
            const float bnm = sm[O_BNM + c], bnb = sm[O_BNB + c];
            float a0 = __uint_as_float(u0) + alb, a1 = __uint_as_float(u1) + alb;
            float a2 = __uint_as_float(u2) + alb, a3 = __uint_as_float(u3) + alb;
            float y0 = (a0 * p0 - bnm) * bni + bnb;
            float y1 = (a1 * p1 - bnm) * bni + bnb;
            float y2 = (a2 * p2 - bnm) * bni + bnb;
            float y3 = (a3 * p3 - bnm) * bni + bnb;
            float4 r;
            r.x = y0 * __fdividef(1.f, 1.f + __expf(-y0));
            r.y = y1 * __fdividef(1.f, 1.f + __expf(-y1));
            r.z = y2 * __fdividef(1.f, 1.f + __expf(-y2));
            r.w = y3 * __fdividef(1.f, 1.f + __expf(-y3));
            *(float4*)(out + ((bz * 64 + c) * IMG + row) * IMG + gcol) = r;
        }
    }
}

extern "C" void kernel_launch(void* const* d_in, const int* in_sizes, int n_in,
                              void* d_out, int out_size) {
    cudaFuncSetAttribute(sac_kernel, cudaFuncAttributeMaxDynamicSharedMemorySize,
                         SMEM_F * sizeof(float));
    dim3 grid(3, 24, 4);
    sac_kernel<<<grid, NT, SMEM_F * sizeof(float)>>>(
        (const float*)d_in[0],  (const float*)d_in[1], (const float*)d_in[2],
        (const float*)d_in[3],  (const float*)d_in[4], (const float*)d_in[5],
        (const float*)d_in[6],  (const float*)d_in[7], (const float*)d_in[8],
        (const float*)d_in[9],  (const float*)d_in[10], (float*)d_out);
}